// round 3
// baseline (speedup 1.0000x reference)
#include <cuda_runtime.h>
#include <cstdint>

#define BATCHES 8
#define NB      32768
#define NCLS    81
#define PRE_K   2048
#define CAP     4096
#define MAX_OUT 200
#define SB_ANCH 128
#define HREP    8

// ---------------- scratch (device globals) ---------------------------------
__device__ unsigned long long g_keys[BATCHES * NB];   // (score_bits<<32)|(NB-1-idx), 0 if invalid
__device__ unsigned char      g_cat [BATCHES * NB];   // argmax class

// ---------------- kernel 1: score/argmax, TMA-staged -----------------------
__global__ void __launch_bounds__(SB_ANCH)
score_kernel(const float* __restrict__ confs) {
    __shared__ alignas(16) float s[SB_ANCH * NCLS];       // 41472 B
    __shared__ alignas(8)  unsigned long long mbar;

    const unsigned bytes  = SB_ANCH * NCLS * 4;
    unsigned mbar_a = (unsigned)__cvta_generic_to_shared(&mbar);
    unsigned smem_a = (unsigned)__cvta_generic_to_shared(s);
    const int a0 = blockIdx.x * SB_ANCH;

    if (threadIdx.x == 0)
        asm volatile("mbarrier.init.shared.b64 [%0], 1;" :: "r"(mbar_a) : "memory");
    __syncthreads();
    if (threadIdx.x == 0) {
        asm volatile("mbarrier.arrive.expect_tx.shared.b64 _, [%0], %1;"
                     :: "r"(mbar_a), "r"(bytes) : "memory");
        asm volatile("cp.async.bulk.shared::cta.global.mbarrier::complete_tx::bytes [%0], [%1], %2, [%3];"
                     :: "r"(smem_a), "l"(confs + (size_t)a0 * NCLS), "r"(bytes), "r"(mbar_a)
                     : "memory");
    }
    // all threads wait for TMA completion (phase 0)
    unsigned done = 0;
    do {
        asm volatile("{\n\t.reg .pred P;\n\t"
                     "mbarrier.try_wait.parity.acquire.cta.shared::cta.b64 P, [%1], %2, 0x989680;\n\t"
                     "selp.b32 %0, 1, 0, P;\n\t}"
                     : "=r"(done) : "r"(mbar_a), "r"(0u) : "memory");
    } while (!done);

    const float* row = s + threadIdx.x * NCLS;   // stride 81 floats: conflict-free
    float m = -1.0f; int mi = 0;
    #pragma unroll
    for (int j = 0; j < NCLS; j++) {
        float v = row[j];
        if (v > m) { m = v; mi = j; }            // ascending j + '>' keeps first max
    }
    const int a = a0 + threadIdx.x;
    bool valid = (m > 0.05f) && (mi != 0);
    unsigned int n = (unsigned int)a & (NB - 1);
    unsigned long long key = 0ULL;
    if (valid)
        key = (((unsigned long long)__float_as_uint(m)) << 32)
            | (unsigned long long)(NB - 1u - n);
    g_keys[a] = key;
    g_cat[a]  = (unsigned char)mi;
}

// ---------------- kernel 2: fused top-2048 select + sort + NMS + output ----
// dynamic smem layout:
//   [0, 32768)            cand: u64[4096]
//   [32768, 98304)        hist: u32[2048*HREP]   (dead after select)
//   [32768, 65536)        scand: float4[2048]    (union with hist)
//   [65536, 69632)        scls: short[2048]      (union with hist)
__global__ void __launch_bounds__(1024)
topk_nms_kernel(const float* __restrict__ boxes, float* __restrict__ out, int write_cats) {
    extern __shared__ unsigned char dyn[];
    unsigned long long* cand  = (unsigned long long*)dyn;
    unsigned int*       hist  = (unsigned int*)(dyn + 32768);
    float4*             scand = (float4*)(dyn + 32768);
    short*              scls  = (short*)(dyn + 65536);

    __shared__ unsigned int wsum[32];
    __shared__ unsigned int sh_t, sh_above, sh_cnt;
    __shared__ short kept_idx[MAX_OUT];
    __shared__ int   sh_nk;

    const int b = blockIdx.x;
    const unsigned long long* keys = g_keys + (size_t)b * NB;
    const int tid  = threadIdx.x;
    const int lane = tid & 31;
    const int warp = tid >> 5;
    const int rep  = warp & (HREP - 1);

    // ---- 3-pass radix select on score bits ----
    unsigned int prefix = 0;
    int          prefshift = 32;
    unsigned int above = 0;
    const int shifts[3]  = {21, 10, 0};
    const int bitsArr[3] = {11, 11, 10};

    for (int p = 0; p < 3; p++) {
        const int bins = 1 << bitsArr[p];
        for (int i = tid; i < bins * HREP; i += 1024) hist[i] = 0;
        __syncthreads();

        for (int i = tid; i < NB; i += 1024) {
            unsigned int sb = (unsigned int)(keys[i] >> 32);
            bool cond;
            if (prefshift >= 32) cond = true;
            else cond = ((sb >> prefshift) == prefix);
            unsigned int bucket = cond ? ((sb >> shifts[p]) & (unsigned)(bins - 1))
                                       : 0xFFFFFFFFu;
            unsigned mm = __match_any_sync(0xffffffffu, bucket);
            if (bucket != 0xFFFFFFFFu && (__ffs(mm) - 1) == lane)
                atomicAdd(&hist[bucket * HREP + rep], (unsigned)__popc(mm));
        }
        __syncthreads();
        // reduce replicas into replica 0
        for (int t = tid; t < bins; t += 1024) {
            unsigned sum = 0;
            #pragma unroll
            for (int r = 0; r < HREP; r++) sum += hist[t * HREP + r];
            hist[t * HREP] = sum;
        }
        __syncthreads();

        // boundary bucket from the top via reversed prefix scan
        const unsigned int K = PRE_K - above;
        const int chunk = bins >> 10;           // 2 or 1
        const int base_r = tid * (chunk ? chunk : 1);
        unsigned int v0 = 0, v1 = 0;
        if (base_r < bins)  v0 = hist[(bins - 1 - base_r) * HREP];
        if (chunk == 2)     v1 = hist[(bins - 2 - base_r) * HREP];
        unsigned int lsum = v0 + v1;
        unsigned int sc = lsum;
        #pragma unroll
        for (int off = 1; off < 32; off <<= 1) {
            unsigned int t = __shfl_up_sync(0xffffffffu, sc, off);
            if (lane >= off) sc += t;
        }
        if (lane == 31) wsum[warp] = sc;
        __syncthreads();
        if (warp == 0) {
            unsigned int ws = wsum[lane];
            #pragma unroll
            for (int off = 1; off < 32; off <<= 1) {
                unsigned int t = __shfl_up_sync(0xffffffffu, ws, off);
                if (lane >= off) ws += t;
            }
            wsum[lane] = ws;
        }
        __syncthreads();
        unsigned int excl = sc - lsum + (warp ? wsum[warp - 1] : 0u);
        unsigned int run = excl;
        if (run < K && run + v0 >= K) { sh_t = (unsigned)(bins - 1 - base_r); sh_above = run; }
        run += v0;
        if (chunk == 2) {
            if (run < K && run + v1 >= K) { sh_t = (unsigned)(bins - 2 - base_r); sh_above = run; }
        }
        __syncthreads();
        above += sh_above;
        prefix = (prefix << bitsArr[p]) | sh_t;
        prefshift = shifts[p];
        __syncthreads();
    }
    const unsigned int Tsb = prefix;   // score-bits of 2048th largest

    // ---- compaction of items with sb >= Tsb ----
    if (tid == 0) sh_cnt = 0;
    __syncthreads();
    for (int i = tid; i < NB; i += 1024) {
        unsigned long long k = keys[i];
        unsigned int sb = (unsigned int)(k >> 32);
        bool c = (sb >= Tsb) && (sb != 0u);
        unsigned bal = __ballot_sync(0xffffffffu, c);
        if (bal) {
            int leader = __ffs(bal) - 1;
            unsigned int basep = 0;
            if (lane == leader) basep = atomicAdd(&sh_cnt, (unsigned)__popc(bal));
            basep = __shfl_sync(0xffffffffu, basep, leader);
            if (c) {
                unsigned int pos = basep + (unsigned)__popc(bal & ((1u << lane) - 1u));
                if (pos < CAP) cand[pos] = k;
            }
        }
    }
    __syncthreads();
    unsigned int cnt = sh_cnt; if (cnt > CAP) cnt = CAP;
    for (int i = tid; i < CAP; i += 1024) if (i >= (int)cnt) cand[i] = 0ULL;
    __syncthreads();

    // ---- hybrid bitonic sort (descending), n = 4096 ----
    // phase 1: k = 2..32 entirely in registers via shfl
    {
        unsigned long long v[4];
        #pragma unroll
        for (int s = 0; s < 4; s++) v[s] = cand[s * 1024 + tid];
        #pragma unroll
        for (int k = 2; k <= 32; k <<= 1) {
            #pragma unroll
            for (int j = k >> 1; j >= 1; j >>= 1) {
                #pragma unroll
                for (int s = 0; s < 4; s++) {
                    int i = s * 1024 + tid;
                    unsigned long long o = __shfl_xor_sync(0xffffffffu, v[s], j);
                    bool up    = ((i & k) == 0);
                    bool lower = ((i & j) == 0);
                    unsigned long long mx = v[s] > o ? v[s] : o;
                    unsigned long long mn = v[s] > o ? o : v[s];
                    v[s] = (up == lower) ? mx : mn;
                }
            }
        }
        #pragma unroll
        for (int s = 0; s < 4; s++) cand[s * 1024 + tid] = v[s];
    }
    __syncthreads();
    // phase 2: k = 64..4096; j>=32 via smem, j<=16 via shfl
    for (int k = 64; k <= CAP; k <<= 1) {
        for (int j = k >> 1; j >= 32; j >>= 1) {
            #pragma unroll
            for (int s0 = 0; s0 < CAP; s0 += 1024) {
                int i = s0 + tid;
                int l = i ^ j;
                if (l > i) {
                    unsigned long long a = cand[i], bb = cand[l];
                    bool up = ((i & k) == 0);
                    if ((a < bb) == up) { cand[i] = bb; cand[l] = a; }
                }
            }
            __syncthreads();
        }
        {
            unsigned long long v[4];
            #pragma unroll
            for (int s = 0; s < 4; s++) v[s] = cand[s * 1024 + tid];
            #pragma unroll
            for (int j = 16; j >= 1; j >>= 1) {
                #pragma unroll
                for (int s = 0; s < 4; s++) {
                    int i = s * 1024 + tid;
                    unsigned long long o = __shfl_xor_sync(0xffffffffu, v[s], j);
                    bool up    = ((i & k) == 0);
                    bool lower = ((i & j) == 0);
                    unsigned long long mx = v[s] > o ? v[s] : o;
                    unsigned long long mn = v[s] > o ? o : v[s];
                    v[s] = (up == lower) ? mx : mn;
                }
            }
            #pragma unroll
            for (int s = 0; s < 4; s++) cand[s * 1024 + tid] = v[s];
        }
        __syncthreads();
    }

    // ---- stage candidate boxes/classes (hist region now dead) ----
    const float*         bxs  = boxes + (size_t)b * NB * 4;
    const unsigned char* cats = g_cat + (size_t)b * NB;
    for (int i = tid; i < PRE_K; i += 1024) {
        unsigned long long k = cand[i];
        if (k == 0ULL) {
            scls[i] = -1;
            scand[i] = make_float4(0.f, 0.f, 0.f, 0.f);
        } else {
            int idx = (NB - 1) - (int)(unsigned int)k;
            scand[i] = *(const float4*)(bxs + (size_t)idx * 4);
            scls[i]  = (short)cats[idx];
        }
    }
    __syncthreads();

    // ---- warp 0: order-exact greedy NMS, register-resident kept list ----
    if (tid < 32) {
        float kx1[7], ky1[7], kx2[7], ky2[7], kar[7];
        short kcl[7];
        int nk = 0;
        for (int i = 0; i < PRE_K && nk < MAX_OUT; i++) {
            short ci = scls[i];
            if (ci < 0) break;             // sorted desc: zero tail
            float4 bb = scand[i];
            float ar = fmaxf(bb.z - bb.x, 0.f) * fmaxf(bb.w - bb.y, 0.f);
            bool sup = false;
            const int ns = (nk + 31) >> 5;
            #pragma unroll
            for (int s = 0; s < 7; s++) {
                if (s >= ns) break;
                if ((s * 32 + lane) < nk && kcl[s] == ci) {
                    float ix1 = fmaxf(bb.x, kx1[s]);
                    float iy1 = fmaxf(bb.y, ky1[s]);
                    float ix2 = fminf(bb.z, kx2[s]);
                    float iy2 = fminf(bb.w, ky2[s]);
                    float inter = fmaxf(ix2 - ix1, 0.f) * fmaxf(iy2 - iy1, 0.f);
                    float uni   = ar + kar[s] - inter;
                    if (inter / fmaxf(uni, 1e-9f) > 0.5f) sup = true;
                }
            }
            sup = __any_sync(0xffffffffu, sup);
            if (!sup) {
                int slot = nk >> 5;
                if ((nk & 31) == lane) {
                    #pragma unroll
                    for (int s = 0; s < 7; s++) {
                        if (slot == s) {
                            kx1[s] = bb.x; ky1[s] = bb.y;
                            kx2[s] = bb.z; ky2[s] = bb.w;
                            kar[s] = ar;   kcl[s] = ci;
                        }
                    }
                }
                if (lane == 0) kept_idx[nk] = (short)i;
                nk++;
            }
        }
        if (lane == 0) sh_nk = nk;
    }
    __syncthreads();

    // ---- output ----
    const int nk = sh_nk;
    float* out5 = out + (size_t)b * MAX_OUT * 5;
    float* ocat = out + (size_t)BATCHES * MAX_OUT * 5 + (size_t)b * MAX_OUT;
    for (int k0 = tid; k0 < MAX_OUT; k0 += 1024) {
        float vx1 = 0, vy1 = 0, vx2 = 0, vy2 = 0, vs = 0, vc = 0;
        if (k0 < nk) {
            int i = kept_idx[k0];
            float4 bb = scand[i];
            vx1 = bb.x; vy1 = bb.y; vx2 = bb.z; vy2 = bb.w;
            vs  = __uint_as_float((unsigned int)(cand[i] >> 32));
            vc  = (float)scls[i];
        }
        out5[k0 * 5 + 0] = vx1;
        out5[k0 * 5 + 1] = vy1;
        out5[k0 * 5 + 2] = vx2;
        out5[k0 * 5 + 3] = vy2;
        out5[k0 * 5 + 4] = vs;
        if (write_cats) ocat[k0] = vc;
    }
}

// ---------------- launch ----------------------------------------------------
extern "C" void kernel_launch(void* const* d_in, const int* in_sizes, int n_in,
                              void* d_out, int out_size) {
    const float* boxes = (const float*)d_in[0];
    const float* confs = (const float*)d_in[1];
    if (n_in >= 2 && in_sizes[0] > in_sizes[1]) {
        boxes = (const float*)d_in[1];
        confs = (const float*)d_in[0];
    }
    float* out = (float*)d_out;

    cudaMemsetAsync(d_out, 0, (size_t)out_size * sizeof(float), 0);

    score_kernel<<<(BATCHES * NB) / SB_ANCH, SB_ANCH>>>(confs);

    const int dyn_bytes = 32768 + 2048 * HREP * 4;   // 98304
    cudaFuncSetAttribute(topk_nms_kernel,
                         cudaFuncAttributeMaxDynamicSharedMemorySize, dyn_bytes);
    int write_cats = (out_size >= BATCHES * MAX_OUT * 6) ? 1 : 0;
    topk_nms_kernel<<<BATCHES, 1024, dyn_bytes>>>(boxes, out, write_cats);
}

// round 4
// speedup vs baseline: 1.1531x; 1.1531x over previous
#include <cuda_runtime.h>
#include <cstdint>

#define BATCHES 8
#define NB      32768
#define NCLS    81
#define PRE_K   2048
#define CAP     4096
#define MAX_OUT 200
#define SB_ANCH 128
#define NBINS   16384
#define BINBASE 0x3D4CCu          /* bits(0.05f) >> 12 */
#define PADIDX(i) ((i) + ((i) >> 4))

// ---------------- scratch (device globals) ---------------------------------
__device__ unsigned long long g_keys[BATCHES * NB];   // (score_bits<<32)|(NB-1-idx), 0 if invalid
__device__ unsigned char      g_cat [BATCHES * NB];   // argmax class
__device__ unsigned int       g_hist[BATCHES * NBINS];// per-batch score-bucket histogram

// ---------------- kernel 1: score/argmax (TMA-staged) + histogram ----------
__global__ void __launch_bounds__(SB_ANCH)
score_kernel(const float* __restrict__ confs) {
    __shared__ alignas(16) float s[SB_ANCH * NCLS];       // 41472 B
    __shared__ alignas(8)  unsigned long long mbar;

    const unsigned bytes  = SB_ANCH * NCLS * 4;
    unsigned mbar_a = (unsigned)__cvta_generic_to_shared(&mbar);
    unsigned smem_a = (unsigned)__cvta_generic_to_shared(s);
    const int a0 = blockIdx.x * SB_ANCH;

    if (threadIdx.x == 0)
        asm volatile("mbarrier.init.shared.b64 [%0], 1;" :: "r"(mbar_a) : "memory");
    __syncthreads();
    if (threadIdx.x == 0) {
        asm volatile("mbarrier.arrive.expect_tx.shared.b64 _, [%0], %1;"
                     :: "r"(mbar_a), "r"(bytes) : "memory");
        asm volatile("cp.async.bulk.shared::cta.global.mbarrier::complete_tx::bytes [%0], [%1], %2, [%3];"
                     :: "r"(smem_a), "l"(confs + (size_t)a0 * NCLS), "r"(bytes), "r"(mbar_a)
                     : "memory");
    }
    unsigned done = 0;
    do {
        asm volatile("{\n\t.reg .pred P;\n\t"
                     "mbarrier.try_wait.parity.acquire.cta.shared::cta.b64 P, [%1], %2, 0x989680;\n\t"
                     "selp.b32 %0, 1, 0, P;\n\t}"
                     : "=r"(done) : "r"(mbar_a), "r"(0u) : "memory");
    } while (!done);

    const float* row = s + threadIdx.x * NCLS;   // stride 81 floats: conflict-free
    float m = -1.0f; int mi = 0;
    #pragma unroll
    for (int j = 0; j < NCLS; j++) {
        float v = row[j];
        if (v > m) { m = v; mi = j; }            // ascending j + '>' keeps first max
    }
    const int a = a0 + threadIdx.x;
    bool valid = (m > 0.05f) && (mi != 0);
    unsigned int n = (unsigned int)a & (NB - 1);
    unsigned long long key = 0ULL;
    if (valid) {
        unsigned int sb = __float_as_uint(m);
        key = (((unsigned long long)sb) << 32) | (unsigned long long)(NB - 1u - n);
        unsigned int bucket = (sb >> 12) - BINBASE;   // monotone, < NBINS
        atomicAdd(&g_hist[(a >> 15) * NBINS + bucket], 1u);
    }
    g_keys[a] = key;
    g_cat[a]  = (unsigned char)mi;
}

// ---------------- kernel 2: threshold + compact + sort + NMS + output ------
// dyn smem:
//   [0, 69632)      bins (padded u32[17408])       -- phase A only
//   [0, 32768)      scand float4[2048]             -- phase C (overlay)
//   [32768, 36864)  scls  short[2048]              -- phase C (overlay)
//   [69632, 102400) cand  u64[4096]
__global__ void __launch_bounds__(1024)
topk_nms_kernel(const float* __restrict__ boxes, float* __restrict__ out, int write_cats) {
    extern __shared__ unsigned char dyn[];
    unsigned int*       bins  = (unsigned int*)dyn;
    float4*             scand = (float4*)dyn;
    short*              scls  = (short*)(dyn + 32768);
    unsigned long long* cand  = (unsigned long long*)(dyn + 69632);

    __shared__ unsigned int sarr[1024];
    __shared__ unsigned int wsum[32];
    __shared__ unsigned int sh_Tb, sh_cnt;
    __shared__ short kept_idx[MAX_OUT];
    __shared__ int   sh_nk;

    const int b = blockIdx.x;
    const int tid  = threadIdx.x;
    const int lane = tid & 31;
    const int warp = tid >> 5;

    // ---- A: load histogram, find threshold bucket Tb ----
    const unsigned int* gh = g_hist + (size_t)b * NBINS;
    for (int i = tid; i < NBINS; i += 1024) bins[PADIDX(i)] = gh[i];
    if (tid == 0) { sh_Tb = 0; sh_cnt = 0; }
    __syncthreads();

    unsigned int ls = 0;
    #pragma unroll
    for (int j = 0; j < 16; j++) ls += bins[PADIDX(tid * 16 + j)];
    sarr[1023 - tid] = ls;
    __syncthreads();

    {   // inclusive block scan over sarr (reversed order => suffix sums)
        unsigned int v = sarr[tid], sc = v;
        #pragma unroll
        for (int off = 1; off < 32; off <<= 1) {
            unsigned int t = __shfl_up_sync(0xffffffffu, sc, off);
            if (lane >= off) sc += t;
        }
        if (lane == 31) wsum[warp] = sc;
        __syncthreads();
        if (warp == 0) {
            unsigned int ws = wsum[lane];
            #pragma unroll
            for (int off = 1; off < 32; off <<= 1) {
                unsigned int t = __shfl_up_sync(0xffffffffu, ws, off);
                if (lane >= off) ws += t;
            }
            wsum[lane] = ws;
        }
        __syncthreads();
        unsigned int incl = sc + (warp ? wsum[warp - 1] : 0u);
        sarr[tid] = incl;
    }
    __syncthreads();
    {
        unsigned int sincl = sarr[1023 - tid];    // sum over threads >= tid
        unsigned int run = sincl - ls;            // suffix strictly above my bins
        #pragma unroll
        for (int j = 15; j >= 0; j--) {
            unsigned int c = bins[PADIDX(tid * 16 + j)];
            run += c;
            if (run >= PRE_K && run - c < PRE_K) sh_Tb = (unsigned)(tid * 16 + j);
        }
    }
    __syncthreads();
    const unsigned int Tsb = (sh_Tb + BINBASE) << 12;  // select: sb >= Tsb

    // ---- B: compaction sweep (MLP-4 prefetch), selected -> cand ----
    const unsigned long long* keys = g_keys + (size_t)b * NB;
    for (int base = 0; base < NB; base += 4096) {
        unsigned long long kk[4];
        #pragma unroll
        for (int u = 0; u < 4; u++) kk[u] = keys[base + u * 1024 + tid];
        #pragma unroll
        for (int u = 0; u < 4; u++) {
            unsigned int sb = (unsigned int)(kk[u] >> 32);
            bool c = (sb >= Tsb);
            unsigned bal = __ballot_sync(0xffffffffu, c);
            if (bal) {
                int leader = __ffs(bal) - 1;
                unsigned int basep = 0;
                if (lane == leader) basep = atomicAdd(&sh_cnt, (unsigned)__popc(bal));
                basep = __shfl_sync(0xffffffffu, basep, leader);
                if (c) {
                    unsigned int pos = basep + (unsigned)__popc(bal & ((1u << lane) - 1u));
                    if (pos < CAP) cand[pos] = kk[u];
                }
            }
        }
    }
    __syncthreads();
    unsigned int cnt = sh_cnt; if (cnt > CAP) cnt = CAP;
    for (int i = tid; i < CAP; i += 1024) if (i >= (int)cnt) cand[i] = 0ULL;
    __syncthreads();

    // ---- hybrid bitonic sort (descending), n = 4096 ----
    {
        unsigned long long v[4];
        #pragma unroll
        for (int s = 0; s < 4; s++) v[s] = cand[s * 1024 + tid];
        #pragma unroll
        for (int k = 2; k <= 32; k <<= 1) {
            #pragma unroll
            for (int j = k >> 1; j >= 1; j >>= 1) {
                #pragma unroll
                for (int s = 0; s < 4; s++) {
                    int i = s * 1024 + tid;
                    unsigned long long o = __shfl_xor_sync(0xffffffffu, v[s], j);
                    bool up    = ((i & k) == 0);
                    bool lower = ((i & j) == 0);
                    unsigned long long mx = v[s] > o ? v[s] : o;
                    unsigned long long mn = v[s] > o ? o : v[s];
                    v[s] = (up == lower) ? mx : mn;
                }
            }
        }
        #pragma unroll
        for (int s = 0; s < 4; s++) cand[s * 1024 + tid] = v[s];
    }
    __syncthreads();
    for (int k = 64; k <= CAP; k <<= 1) {
        for (int j = k >> 1; j >= 32; j >>= 1) {
            #pragma unroll
            for (int s0 = 0; s0 < CAP; s0 += 1024) {
                int i = s0 + tid;
                int l = i ^ j;
                if (l > i) {
                    unsigned long long a = cand[i], bb = cand[l];
                    bool up = ((i & k) == 0);
                    if ((a < bb) == up) { cand[i] = bb; cand[l] = a; }
                }
            }
            __syncthreads();
        }
        {
            unsigned long long v[4];
            #pragma unroll
            for (int s = 0; s < 4; s++) v[s] = cand[s * 1024 + tid];
            #pragma unroll
            for (int j = 16; j >= 1; j >>= 1) {
                #pragma unroll
                for (int s = 0; s < 4; s++) {
                    int i = s * 1024 + tid;
                    unsigned long long o = __shfl_xor_sync(0xffffffffu, v[s], j);
                    bool up    = ((i & k) == 0);
                    bool lower = ((i & j) == 0);
                    unsigned long long mx = v[s] > o ? v[s] : o;
                    unsigned long long mn = v[s] > o ? o : v[s];
                    v[s] = (up == lower) ? mx : mn;
                }
            }
            #pragma unroll
            for (int s = 0; s < 4; s++) cand[s * 1024 + tid] = v[s];
        }
        __syncthreads();
    }

    // ---- C: stage candidate boxes/classes (bins region now dead) ----
    const float*         bxs  = boxes + (size_t)b * NB * 4;
    const unsigned char* cats = g_cat + (size_t)b * NB;
    for (int i = tid; i < PRE_K; i += 1024) {
        unsigned long long k = cand[i];
        if (k == 0ULL) {
            scls[i] = -1;
            scand[i] = make_float4(0.f, 0.f, 0.f, 0.f);
        } else {
            int idx = (NB - 1) - (int)(unsigned int)k;
            scand[i] = *(const float4*)(bxs + (size_t)idx * 4);
            scls[i]  = (short)cats[idx];
        }
    }
    __syncthreads();

    // ---- warp 0: order-exact greedy NMS, register-resident kept list ----
    if (tid < 32) {
        float kx1[7], ky1[7], kx2[7], ky2[7], kar[7];
        short kcl[7];
        int nk = 0;
        for (int i = 0; i < PRE_K && nk < MAX_OUT; i++) {
            short ci = scls[i];
            if (ci < 0) break;             // sorted desc: zero tail
            float4 bb = scand[i];
            float ar = fmaxf(bb.z - bb.x, 0.f) * fmaxf(bb.w - bb.y, 0.f);
            bool sup = false;
            const int ns = (nk + 31) >> 5;
            #pragma unroll
            for (int s = 0; s < 7; s++) {
                if (s >= ns) break;
                if ((s * 32 + lane) < nk && kcl[s] == ci) {
                    float ix1 = fmaxf(bb.x, kx1[s]);
                    float iy1 = fmaxf(bb.y, ky1[s]);
                    float ix2 = fminf(bb.z, kx2[s]);
                    float iy2 = fminf(bb.w, ky2[s]);
                    float inter = fmaxf(ix2 - ix1, 0.f) * fmaxf(iy2 - iy1, 0.f);
                    float uni   = ar + kar[s] - inter;
                    if (inter / fmaxf(uni, 1e-9f) > 0.5f) sup = true;
                }
            }
            sup = __any_sync(0xffffffffu, sup);
            if (!sup) {
                int slot = nk >> 5;
                if ((nk & 31) == lane) {
                    #pragma unroll
                    for (int s = 0; s < 7; s++) {
                        if (slot == s) {
                            kx1[s] = bb.x; ky1[s] = bb.y;
                            kx2[s] = bb.z; ky2[s] = bb.w;
                            kar[s] = ar;   kcl[s] = ci;
                        }
                    }
                }
                if (lane == 0) kept_idx[nk] = (short)i;
                nk++;
            }
        }
        if (lane == 0) sh_nk = nk;
    }
    __syncthreads();

    // ---- output ----
    const int nk = sh_nk;
    float* out5 = out + (size_t)b * MAX_OUT * 5;
    float* ocat = out + (size_t)BATCHES * MAX_OUT * 5 + (size_t)b * MAX_OUT;
    for (int k0 = tid; k0 < MAX_OUT; k0 += 1024) {
        float vx1 = 0, vy1 = 0, vx2 = 0, vy2 = 0, vs = 0, vc = 0;
        if (k0 < nk) {
            int i = kept_idx[k0];
            float4 bb = scand[i];
            vx1 = bb.x; vy1 = bb.y; vx2 = bb.z; vy2 = bb.w;
            vs  = __uint_as_float((unsigned int)(cand[i] >> 32));
            vc  = (float)scls[i];
        }
        out5[k0 * 5 + 0] = vx1;
        out5[k0 * 5 + 1] = vy1;
        out5[k0 * 5 + 2] = vx2;
        out5[k0 * 5 + 3] = vy2;
        out5[k0 * 5 + 4] = vs;
        if (write_cats) ocat[k0] = vc;
    }
}

// ---------------- launch ----------------------------------------------------
extern "C" void kernel_launch(void* const* d_in, const int* in_sizes, int n_in,
                              void* d_out, int out_size) {
    const float* boxes = (const float*)d_in[0];
    const float* confs = (const float*)d_in[1];
    if (n_in >= 2 && in_sizes[0] > in_sizes[1]) {
        boxes = (const float*)d_in[1];
        confs = (const float*)d_in[0];
    }
    float* out = (float*)d_out;

    cudaMemsetAsync(d_out, 0, (size_t)out_size * sizeof(float), 0);
    void* hp = nullptr;
    cudaGetSymbolAddress(&hp, g_hist);
    cudaMemsetAsync(hp, 0, sizeof(unsigned int) * BATCHES * NBINS, 0);

    score_kernel<<<(BATCHES * NB) / SB_ANCH, SB_ANCH>>>(confs);

    const int dyn_bytes = 69632 + CAP * 8;   // 102400
    cudaFuncSetAttribute(topk_nms_kernel,
                         cudaFuncAttributeMaxDynamicSharedMemorySize, dyn_bytes);
    int write_cats = (out_size >= BATCHES * MAX_OUT * 6) ? 1 : 0;
    topk_nms_kernel<<<BATCHES, 1024, dyn_bytes>>>(boxes, out, write_cats);
}